// round 12
// baseline (speedup 1.0000x reference)
#include <cuda_runtime.h>
#include <cuda_bf16.h>
#include <cstdint>
#include <math.h>

#define BSZ 16384
#define TN  10
#define IN_ 184
#define HN  128
#define WST 384          // weight-cat row stride (bf16 elems)

// ------------------------- scratch (__device__ globals) -------------------------
__device__ __nv_bfloat16 g_xh[(size_t)BSZ * TN * 192];
__device__ __nv_bfloat16 g_xl[(size_t)BSZ * TN * 192];
__device__ __nv_bfloat16 g_o1h[(size_t)BSZ * TN * 256];
__device__ __nv_bfloat16 g_o1l[(size_t)BSZ * TN * 256];
__device__ __nv_bfloat16 g_o2h[(size_t)BSZ * TN * 256];
__device__ __nv_bfloat16 g_o2l[(size_t)BSZ * TN * 256];
__device__ __nv_bfloat16 g_wh[(size_t)4 * 512 * WST];
__device__ __nv_bfloat16 g_wl[(size_t)4 * 512 * WST];
__device__ float g_cf[(size_t)BSZ * HN];
__device__ float g_cb[(size_t)BSZ * HN];
__device__ float g_pooled[(size_t)BSZ * 512];

// ------------------------- small helpers -------------------------
__device__ __forceinline__ uint32_t smem_u32(const void* p) {
    uint32_t a;
    asm("{ .reg .u64 t; cvta.to.shared.u64 t, %1; cvt.u32.u64 %0, t; }" : "=r"(a) : "l"(p));
    return a;
}
__device__ __forceinline__ void ldsm_x4(uint32_t& r0, uint32_t& r1, uint32_t& r2, uint32_t& r3, uint32_t addr) {
    asm volatile("ldmatrix.sync.aligned.m8n8.x4.shared.b16 {%0,%1,%2,%3}, [%4];"
                 : "=r"(r0), "=r"(r1), "=r"(r2), "=r"(r3) : "r"(addr));
}
__device__ __forceinline__ void mma16816(float* d, const uint32_t* a, const uint32_t* b) {
    asm volatile("mma.sync.aligned.m16n8k16.row.col.f32.bf16.bf16.f32 "
                 "{%0,%1,%2,%3}, {%4,%5,%6,%7}, {%8,%9}, {%0,%1,%2,%3};"
                 : "+f"(d[0]), "+f"(d[1]), "+f"(d[2]), "+f"(d[3])
                 : "r"(a[0]), "r"(a[1]), "r"(a[2]), "r"(a[3]), "r"(b[0]), "r"(b[1]));
}
__device__ __forceinline__ void cpa16(uint32_t saddr, const void* gptr) {
    asm volatile("cp.async.cg.shared.global [%0], [%1], 16;" :: "r"(saddr), "l"(gptr));
}
__device__ __forceinline__ void cpa_commit() { asm volatile("cp.async.commit_group;"); }
__device__ __forceinline__ void cpa_wait1()  { asm volatile("cp.async.wait_group 1;"); }
__device__ __forceinline__ void cpa_wait0()  { asm volatile("cp.async.wait_group 0;"); }

// ------------------------- split conversions -------------------------
__global__ void split_x_kernel(const float* __restrict__ x,
                               __nv_bfloat16* __restrict__ xh, __nv_bfloat16* __restrict__ xl) {
    long i = (long)blockIdx.x * blockDim.x + threadIdx.x;
    if (i >= (long)BSZ * TN * 192) return;
    int col = (int)(i % 192);
    long bt = i / 192;
    float v = (col < IN_) ? x[bt * IN_ + col] : 0.f;
    __nv_bfloat16 h = __float2bfloat16(v);
    xh[i] = h;
    xl[i] = __float2bfloat16(v - __bfloat162float(h));
}

__global__ void split_w_kernel(const float* __restrict__ a0, const float* __restrict__ h0,
                               const float* __restrict__ a1, const float* __restrict__ h1,
                               const float* __restrict__ a2, const float* __restrict__ h2,
                               const float* __restrict__ a3, const float* __restrict__ h3,
                               __nv_bfloat16* __restrict__ wh, __nv_bfloat16* __restrict__ wl) {
    long i = (long)blockIdx.x * blockDim.x + threadIdx.x;
    if (i >= (long)4 * 512 * WST) return;
    int col = (int)(i % WST);
    int r = (int)((i / WST) % 512);
    int cfg = (int)(i / ((long)512 * WST));
    const float* wih; const float* whh; int kx, hoff;
    switch (cfg) {
        case 0: wih = a0; whh = h0; kx = 184; hoff = 192; break;
        case 1: wih = a1; whh = h1; kx = 184; hoff = 192; break;
        case 2: wih = a2; whh = h2; kx = 256; hoff = 256; break;
        default: wih = a3; whh = h3; kx = 256; hoff = 256; break;
    }
    float v = 0.f;
    if (col < kx)                             v = wih[(long)r * kx + col];
    else if (col >= hoff && col < hoff + 128) v = whh[(long)r * 128 + (col - hoff)];
    __nv_bfloat16 h = __float2bfloat16(v);
    wh[i] = h;
    wl[i] = __float2bfloat16(v - __bfloat162float(h));
}

// ------------------------- fused HMMA LSTM step (cp.async 2-stage pipeline) -----
// Block: 128 batch rows x 128 cols (32 units x 4 gates, col = 4*unit + gate).
// 256 threads = 8 warps in 2(m) x 4(n); warp tile 64 x 32.
// K processed in 32-col chunks, double-buffered via cp.async.
struct DirP {
    const __nv_bfloat16 *axh, *axl;
    const __nv_bfloat16 *ahh, *ahl;
    const __nv_bfloat16 *wh, *wl;
    const float *bih, *bhh;
    float* cbuf;
    __nv_bfloat16 *oh, *ol;
    long xstride, hstride, ostride;
    int xchunks, nchunks;            // in 32-col chunks
};
struct StepP { DirP d[2]; int first; };

#define LDA 40                        // padded smem row stride (bf16) for 32-col tiles
#define T32 (128 * LDA)               // elems per tile
#define STG (4 * T32)                 // elems per stage (Ah,Al,Bh,Bl)
#define SMEM_DYN (2 * STG * 2 + 512)  // 2 stages + bias

__global__ __launch_bounds__(256, 2)
void lstm_mma(StepP sp)
{
    extern __shared__ char dyn[];
    float* sBias = (float*)(dyn + 2 * STG * 2);
    const uint32_t sb = smem_u32(dyn);

    const DirP& P = sp.d[blockIdx.z];
    const int first = sp.first;
    const int tid = threadIdx.x, lane = tid & 31, warp = tid >> 5;
    const int wm = warp >> 2, wn = warp & 3;
    const int b0 = blockIdx.x * 128, n0 = blockIdx.y * 32;

    if (tid < 128) {
        int u = tid >> 2, g = tid & 3;
        int wr = g * 128 + n0 + u;
        sBias[tid] = P.bih[wr] + P.bhh[wr];
    }

    float acc[4][4][4];
#pragma unroll
    for (int i = 0; i < 4; ++i)
#pragma unroll
        for (int j = 0; j < 4; ++j)
#pragma unroll
            for (int k = 0; k < 4; ++k) acc[i][j][k] = 0.f;

    const int nc = first ? P.xchunks : P.nchunks;

    // per-thread load slots: idx = tid + it*256 (it<2): row = idx>>2, gc = idx&3
    const int r0 = tid >> 2, gc0 = (tid & 3) * 8;             // it=0
    const int r1 = (tid + 256) >> 2, gc1 = gc0;               // it=1 (same gc)
    const int wrow0 = (r0 & 3) * 128 + n0 + (r0 >> 2);        // gathered weight rows
    const int wrow1 = (r1 & 3) * 128 + n0 + (r1 >> 2);

    // issue loads for chunk c into stage s
    auto load_chunk = [&](int c, int s) {
        const uint32_t st = sb + (uint32_t)s * STG * 2;
        const bool isx = (c < P.xchunks);
        const long acol = (long)(isx ? c : (c - P.xchunks)) * 32;
        const long astr = isx ? P.xstride : P.hstride;
        const __nv_bfloat16* abh = isx ? P.axh : P.ahh;
        const __nv_bfloat16* abl = isx ? P.axl : P.ahl;
        const long wcol = (long)c * 32;
        // A tiles
        cpa16(st + ((uint32_t)r0 * LDA + gc0) * 2,            abh + (long)(b0 + r0) * astr + acol + gc0);
        cpa16(st + ((uint32_t)r1 * LDA + gc1) * 2,            abh + (long)(b0 + r1) * astr + acol + gc1);
        cpa16(st + (T32 + (uint32_t)r0 * LDA + gc0) * 2,      abl + (long)(b0 + r0) * astr + acol + gc0);
        cpa16(st + (T32 + (uint32_t)r1 * LDA + gc1) * 2,      abl + (long)(b0 + r1) * astr + acol + gc1);
        // B tiles (gathered weight rows)
        cpa16(st + (2 * T32 + (uint32_t)r0 * LDA + gc0) * 2,  P.wh + (long)wrow0 * WST + wcol + gc0);
        cpa16(st + (2 * T32 + (uint32_t)r1 * LDA + gc1) * 2,  P.wh + (long)wrow1 * WST + wcol + gc1);
        cpa16(st + (3 * T32 + (uint32_t)r0 * LDA + gc0) * 2,  P.wl + (long)wrow0 * WST + wcol + gc0);
        cpa16(st + (3 * T32 + (uint32_t)r1 * LDA + gc1) * 2,  P.wl + (long)wrow1 * WST + wcol + gc1);
        cpa_commit();
    };

    // ldmatrix lane-address components
    const int aRow = (lane & 15), aKo = (lane >> 4) * 8;
    const int bRow = (lane & 7);
    const int bKo  = ((lane >> 3) & 1) * 8;
    const int bNs  = ((lane >> 4) & 1) * 8;

    load_chunk(0, 0);

    for (int c = 0; c < nc; ++c) {
        const int cs = c & 1;
        if (c + 1 < nc) { load_chunk(c + 1, cs ^ 1); cpa_wait1(); }
        else            { cpa_wait0(); }
        __syncthreads();

        const uint32_t st = sb + (uint32_t)cs * STG * 2;
        const uint32_t uAh = st, uAl = st + T32 * 2, uBh = st + 2 * T32 * 2, uBl = st + 3 * T32 * 2;

#pragma unroll
        for (int kk = 0; kk < 2; ++kk) {
            const uint32_t aoff = ((uint32_t)(wm * 64 + aRow) * LDA + kk * 16 + aKo) * 2;
            uint32_t ah[4][4], al[4][4];
#pragma unroll
            for (int mi = 0; mi < 4; ++mi) {
                ldsm_x4(ah[mi][0], ah[mi][1], ah[mi][2], ah[mi][3], uAh + aoff + mi * 16 * LDA * 2);
                ldsm_x4(al[mi][0], al[mi][1], al[mi][2], al[mi][3], uAl + aoff + mi * 16 * LDA * 2);
            }
#pragma unroll
            for (int np = 0; np < 2; ++np) {
                const uint32_t boff = ((uint32_t)(wn * 32 + np * 16 + bNs + bRow) * LDA + kk * 16 + bKo) * 2;
                uint32_t bh[4], bl[4];
                ldsm_x4(bh[0], bh[1], bh[2], bh[3], uBh + boff);
                ldsm_x4(bl[0], bl[1], bl[2], bl[3], uBl + boff);
#pragma unroll
                for (int mi = 0; mi < 4; ++mi) {
                    mma16816(acc[mi][np * 2 + 0], ah[mi], bh + 0);
                    mma16816(acc[mi][np * 2 + 0], al[mi], bh + 0);
                    mma16816(acc[mi][np * 2 + 0], ah[mi], bl + 0);
                    mma16816(acc[mi][np * 2 + 1], ah[mi], bh + 2);
                    mma16816(acc[mi][np * 2 + 1], al[mi], bh + 2);
                    mma16816(acc[mi][np * 2 + 1], ah[mi], bl + 2);
                }
            }
        }
        __syncthreads();
    }

    // ---- epilogue: pair-exchange gates, LSTM pointwise, write h (hi/lo) + c ----
    const bool odd = (lane & 1);
    const int rbase = lane >> 2;
    const int usub = (lane >> 1) & 1;
#pragma unroll
    for (int mi = 0; mi < 4; ++mi) {
#pragma unroll
        for (int ni = 0; ni < 4; ++ni) {
            float c0 = acc[mi][ni][0], c1 = acc[mi][ni][1], c2 = acc[mi][ni][2], c3 = acc[mi][ni][3];
            float s0 = __shfl_xor_sync(0xFFFFFFFFu, c0, 1);
            float s1 = __shfl_xor_sync(0xFFFFFFFFu, c1, 1);
            float s2 = __shfl_xor_sync(0xFFFFFFFFu, c2, 1);
            float s3 = __shfl_xor_sync(0xFFFFFFFFu, c3, 1);
            float vi, vf, vg, vo;
            int r;
            if (!odd) { vi = c0; vf = c1; vg = s0; vo = s1; r = rbase; }
            else      { vi = s2; vf = s3; vg = c2; vo = c3; r = rbase + 8; }
            const int ul = ((wn * 32 + ni * 8) >> 2) + usub;
            const float4 bb = *(const float4*)&sBias[4 * ul];
            vi += bb.x; vf += bb.y; vg += bb.z; vo += bb.w;
            float ig = 1.f / (1.f + __expf(-vi));
            float fg = 1.f / (1.f + __expf(-vf));
            float gg = tanhf(vg);
            float og = 1.f / (1.f + __expf(-vo));
            const long b = b0 + wm * 64 + mi * 16 + r;
            const int gu = n0 + ul;
            float cp = first ? 0.f : P.cbuf[b * HN + gu];
            float cn = fg * cp + ig * gg;
            P.cbuf[b * HN + gu] = cn;
            float h = og * tanhf(cn);
            __nv_bfloat16 hh = __float2bfloat16(h);
            P.oh[b * P.ostride + gu] = hh;
            P.ol[b * P.ostride + gu] = __float2bfloat16(h - __bfloat162float(hh));
        }
    }
}

// ------------------------- temporal max-pool -------------------------
__global__ void pool_kernel(const __nv_bfloat16* __restrict__ oh,
                            const __nv_bfloat16* __restrict__ ol,
                            float* __restrict__ pooled)
{
    long idx = (long)blockIdx.x * blockDim.x + threadIdx.x;
    if (idx >= (long)BSZ * 512) return;
    int b = (int)(idx >> 9);
    int col = (int)(idx & 511);
    int h = col >> 1, p = col & 1;
    long base = ((long)b * TN + p * 5) * 256 + h;
    float m = -1e30f;
#pragma unroll
    for (int s = 0; s < 5; ++s) {
        long i = base + (long)s * 256;
        float v = __bfloat162float(oh[i]) + __bfloat162float(ol[i]);
        m = fmaxf(m, v);
    }
    pooled[idx] = m;
}

// ------------------------- fused FC1(relu)+FC2 -------------------------
__global__ __launch_bounds__(256)
void fc_kernel(const float* __restrict__ pooled,
               const float* __restrict__ w1, const float* __restrict__ b1,
               const float* __restrict__ w2, const float* __restrict__ b2,
               float* __restrict__ outp)
{
    __shared__ float S[64 * 65 + 64 * 64];
    float (*Ws)[65] = (float (*)[65])S;
    float (*Ps)[64] = (float (*)[64])(S + 64 * 65);

    const int tid = threadIdx.x;
    const int b0 = blockIdx.x * 64;
    const int o  = tid & 63;
    const int tg = tid >> 6;

    float acc[16];
#pragma unroll
    for (int r = 0; r < 16; ++r) acc[r] = 0.f;

    for (int kt = 0; kt < 512; kt += 64) {
        for (int e = tid; e < 64 * 64; e += 256) {
            int oo = e >> 6, k = e & 63;
            Ws[k][oo] = w1[(long)oo * 512 + kt + k];
            Ps[oo][k] = pooled[(long)(b0 + oo) * 512 + kt + k];
        }
        __syncthreads();
#pragma unroll 4
        for (int k = 0; k < 64; ++k) {
            float w = Ws[k][o];
#pragma unroll
            for (int r = 0; r < 16; ++r)
                acc[r] = fmaf(Ps[tg * 16 + r][k], w, acc[r]);
        }
        __syncthreads();
    }
    float (*H1)[65] = (float (*)[65])S;
    float bias1 = b1[o];
#pragma unroll
    for (int r = 0; r < 16; ++r)
        H1[tg * 16 + r][o] = fmaxf(acc[r] + bias1, 0.f);
    __syncthreads();
    if (tid < 64) {
        float a2 = b2[0];
#pragma unroll
        for (int oo = 0; oo < 64; ++oo) a2 = fmaf(H1[tid][oo], w2[oo], a2);
        outp[b0 + tid] = a2;
    }
}

// ------------------------- host launcher -------------------------
extern "C" void kernel_launch(void* const* d_in, const int* in_sizes, int n_in,
                              void* d_out, int out_size)
{
    const float* x       = (const float*)d_in[0];
    const float* w_ih1_f = (const float*)d_in[1];
    const float* w_hh1_f = (const float*)d_in[2];
    const float* b_ih1_f = (const float*)d_in[3];
    const float* b_hh1_f = (const float*)d_in[4];
    const float* w_ih1_b = (const float*)d_in[5];
    const float* w_hh1_b = (const float*)d_in[6];
    const float* b_ih1_b = (const float*)d_in[7];
    const float* b_hh1_b = (const float*)d_in[8];
    const float* w_ih2_f = (const float*)d_in[9];
    const float* w_hh2_f = (const float*)d_in[10];
    const float* b_ih2_f = (const float*)d_in[11];
    const float* b_hh2_f = (const float*)d_in[12];
    const float* w_ih2_b = (const float*)d_in[13];
    const float* w_hh2_b = (const float*)d_in[14];
    const float* b_ih2_b = (const float*)d_in[15];
    const float* b_hh2_b = (const float*)d_in[16];
    const float* fc1_w   = (const float*)d_in[17];
    const float* fc1_b   = (const float*)d_in[18];
    const float* fc2_w   = (const float*)d_in[19];
    const float* fc2_b   = (const float*)d_in[20];

    __nv_bfloat16 *xh, *xl, *o1h, *o1l, *o2h, *o2l, *wh, *wl;
    float *cf, *cb, *pooled;
    cudaGetSymbolAddress((void**)&xh, g_xh);   cudaGetSymbolAddress((void**)&xl, g_xl);
    cudaGetSymbolAddress((void**)&o1h, g_o1h); cudaGetSymbolAddress((void**)&o1l, g_o1l);
    cudaGetSymbolAddress((void**)&o2h, g_o2h); cudaGetSymbolAddress((void**)&o2l, g_o2l);
    cudaGetSymbolAddress((void**)&wh, g_wh);   cudaGetSymbolAddress((void**)&wl, g_wl);
    cudaGetSymbolAddress((void**)&cf, g_cf);   cudaGetSymbolAddress((void**)&cb, g_cb);
    cudaGetSymbolAddress((void**)&pooled, g_pooled);

    cudaFuncSetAttribute(lstm_mma, cudaFuncAttributeMaxDynamicSharedMemorySize, SMEM_DYN);

    {
        long n = (long)BSZ * TN * 192;
        split_x_kernel<<<(unsigned)((n + 255) / 256), 256>>>(x, xh, xl);
        long m = (long)4 * 512 * WST;
        split_w_kernel<<<(unsigned)((m + 255) / 256), 256>>>(
            w_ih1_f, w_hh1_f, w_ih1_b, w_hh1_b, w_ih2_f, w_hh2_f, w_ih2_b, w_hh2_b, wh, wl);
    }

    dim3 grid(BSZ / 128, 4, 2), blk(256);
    const long WCFG = (long)512 * WST;

    // ---- layer 1 ----  (x: 6 chunks of 32, h: 4 chunks)
    for (int t = 0; t < TN; ++t) {
        StepP sp;
        sp.first = (t == 0);
        sp.d[0].axh = xh + (long)t * 192;  sp.d[0].axl = xl + (long)t * 192;
        sp.d[0].ahh = t ? o1h + (long)(t - 1) * 256 : o1h;
        sp.d[0].ahl = t ? o1l + (long)(t - 1) * 256 : o1l;
        sp.d[0].wh = wh + 0 * WCFG; sp.d[0].wl = wl + 0 * WCFG;
        sp.d[0].bih = b_ih1_f; sp.d[0].bhh = b_hh1_f;
        sp.d[0].cbuf = cf;
        sp.d[0].oh = o1h + (long)t * 256; sp.d[0].ol = o1l + (long)t * 256;
        sp.d[0].xstride = (long)TN * 192; sp.d[0].hstride = (long)TN * 256; sp.d[0].ostride = (long)TN * 256;
        sp.d[0].xchunks = 6; sp.d[0].nchunks = 10;
        int tt = TN - 1 - t;
        sp.d[1].axh = xh + (long)tt * 192;  sp.d[1].axl = xl + (long)tt * 192;
        sp.d[1].ahh = t ? o1h + (long)(tt + 1) * 256 + HN : o1h;
        sp.d[1].ahl = t ? o1l + (long)(tt + 1) * 256 + HN : o1l;
        sp.d[1].wh = wh + 1 * WCFG; sp.d[1].wl = wl + 1 * WCFG;
        sp.d[1].bih = b_ih1_b; sp.d[1].bhh = b_hh1_b;
        sp.d[1].cbuf = cb;
        sp.d[1].oh = o1h + (long)tt * 256 + HN; sp.d[1].ol = o1l + (long)tt * 256 + HN;
        sp.d[1].xstride = (long)TN * 192; sp.d[1].hstride = (long)TN * 256; sp.d[1].ostride = (long)TN * 256;
        sp.d[1].xchunks = 6; sp.d[1].nchunks = 10;
        lstm_mma<<<grid, blk, SMEM_DYN>>>(sp);
    }

    // ---- layer 2 ----  (x: 8 chunks, h: 4 chunks)
    for (int t = 0; t < TN; ++t) {
        StepP sp;
        sp.first = (t == 0);
        sp.d[0].axh = o1h + (long)t * 256;  sp.d[0].axl = o1l + (long)t * 256;
        sp.d[0].ahh = t ? o2h + (long)(t - 1) * 256 : o2h;
        sp.d[0].ahl = t ? o2l + (long)(t - 1) * 256 : o2l;
        sp.d[0].wh = wh + 2 * WCFG; sp.d[0].wl = wl + 2 * WCFG;
        sp.d[0].bih = b_ih2_f; sp.d[0].bhh = b_hh2_f;
        sp.d[0].cbuf = cf;
        sp.d[0].oh = o2h + (long)t * 256; sp.d[0].ol = o2l + (long)t * 256;
        sp.d[0].xstride = (long)TN * 256; sp.d[0].hstride = (long)TN * 256; sp.d[0].ostride = (long)TN * 256;
        sp.d[0].xchunks = 8; sp.d[0].nchunks = 12;
        int tt = TN - 1 - t;
        sp.d[1].axh = o1h + (long)tt * 256;  sp.d[1].axl = o1l + (long)tt * 256;
        sp.d[1].ahh = t ? o2h + (long)(tt + 1) * 256 + HN : o2h;
        sp.d[1].ahl = t ? o2l + (long)(tt + 1) * 256 + HN : o2l;
        sp.d[1].wh = wh + 3 * WCFG; sp.d[1].wl = wl + 3 * WCFG;
        sp.d[1].bih = b_ih2_b; sp.d[1].bhh = b_hh2_b;
        sp.d[1].cbuf = cb;
        sp.d[1].oh = o2h + (long)tt * 256 + HN; sp.d[1].ol = o2l + (long)tt * 256 + HN;
        sp.d[1].xstride = (long)TN * 256; sp.d[1].hstride = (long)TN * 256; sp.d[1].ostride = (long)TN * 256;
        sp.d[1].xchunks = 8; sp.d[1].nchunks = 12;
        lstm_mma<<<grid, blk, SMEM_DYN>>>(sp);
    }

    pool_kernel<<<(unsigned)(((long)BSZ * 512 + 255) / 256), 256>>>(o2h, o2l, pooled);
    fc_kernel<<<BSZ / 64, 256>>>(pooled, fc1_w, fc1_b, fc2_w, fc2_b, (float*)d_out);
}

// round 13
// speedup vs baseline: 1.0404x; 1.0404x over previous
#include <cuda_runtime.h>
#include <cuda_fp16.h>
#include <cstdint>
#include <math.h>

#define BSZ 16384
#define TN  10
#define IN_ 184
#define HN  128
#define WST 384          // weight-cat row stride (fp16 elems)

// ------------------------- scratch (__device__ globals) -------------------------
__device__ __half g_xh[(size_t)BSZ * TN * 192];
__device__ __half g_xl[(size_t)BSZ * TN * 192];
__device__ __half g_o1h[(size_t)BSZ * TN * 256];
__device__ __half g_o1l[(size_t)BSZ * TN * 256];
__device__ __half g_o2h[(size_t)BSZ * TN * 256];
__device__ __half g_o2l[(size_t)BSZ * TN * 256];
__device__ __half g_w[(size_t)4 * 512 * WST];
__device__ float g_cf[(size_t)BSZ * HN];
__device__ float g_cb[(size_t)BSZ * HN];
__device__ float g_pooled[(size_t)BSZ * 512];

// ------------------------- small helpers -------------------------
__device__ __forceinline__ uint32_t smem_u32(const void* p) {
    uint32_t a;
    asm("{ .reg .u64 t; cvta.to.shared.u64 t, %1; cvt.u32.u64 %0, t; }" : "=r"(a) : "l"(p));
    return a;
}
__device__ __forceinline__ void ldsm_x4(uint32_t& r0, uint32_t& r1, uint32_t& r2, uint32_t& r3, uint32_t addr) {
    asm volatile("ldmatrix.sync.aligned.m8n8.x4.shared.b16 {%0,%1,%2,%3}, [%4];"
                 : "=r"(r0), "=r"(r1), "=r"(r2), "=r"(r3) : "r"(addr));
}
__device__ __forceinline__ void mma16816(float* d, const uint32_t* a, const uint32_t* b) {
    asm volatile("mma.sync.aligned.m16n8k16.row.col.f32.f16.f16.f32 "
                 "{%0,%1,%2,%3}, {%4,%5,%6,%7}, {%8,%9}, {%0,%1,%2,%3};"
                 : "+f"(d[0]), "+f"(d[1]), "+f"(d[2]), "+f"(d[3])
                 : "r"(a[0]), "r"(a[1]), "r"(a[2]), "r"(a[3]), "r"(b[0]), "r"(b[1]));
}

// ------------------------- split conversions -------------------------
__global__ void split_x_kernel(const float* __restrict__ x,
                               __half* __restrict__ xh, __half* __restrict__ xl) {
    long i = (long)blockIdx.x * blockDim.x + threadIdx.x;
    if (i >= (long)BSZ * TN * 192) return;
    int col = (int)(i % 192);
    long bt = i / 192;
    float v = (col < IN_) ? x[bt * IN_ + col] : 0.f;
    __half h = __float2half_rn(v);
    xh[i] = h;
    xl[i] = __float2half_rn(v - __half2float(h));
}

__global__ void conv_w_kernel(const float* __restrict__ a0, const float* __restrict__ h0,
                              const float* __restrict__ a1, const float* __restrict__ h1,
                              const float* __restrict__ a2, const float* __restrict__ h2,
                              const float* __restrict__ a3, const float* __restrict__ h3,
                              __half* __restrict__ w) {
    long i = (long)blockIdx.x * blockDim.x + threadIdx.x;
    if (i >= (long)4 * 512 * WST) return;
    int col = (int)(i % WST);
    int r = (int)((i / WST) % 512);
    int cfg = (int)(i / ((long)512 * WST));
    const float* wih; const float* whh; int kx, hoff;
    switch (cfg) {
        case 0: wih = a0; whh = h0; kx = 184; hoff = 192; break;
        case 1: wih = a1; whh = h1; kx = 184; hoff = 192; break;
        case 2: wih = a2; whh = h2; kx = 256; hoff = 256; break;
        default: wih = a3; whh = h3; kx = 256; hoff = 256; break;
    }
    float v = 0.f;
    if (col < kx)                             v = wih[(long)r * kx + col];
    else if (col >= hoff && col < hoff + 128) v = whh[(long)r * 128 + (col - hoff)];
    w[i] = __float2half_rn(v);
}

// ------------------------- fused HMMA LSTM step -------------------------
// Block: 128 batch rows x 128 cols (32 units x 4 gates, col = 4*unit + gate).
// 256 threads = 8 warps in 2(m) x 4(n); warp tile 64 x 32.
// fp16: activations split hi/lo (exact), weights single fp16. 2 combos.
struct DirP {
    const __half *axh, *axl;
    const __half *ahh, *ahl;
    const __half *w;                  // weight-cat [512][WST]
    const float *bih, *bhh;
    float* cbuf;
    __half *oh, *ol;
    long xstride, hstride, ostride;
    int xchunks, nchunks;             // in 64-col chunks
};
struct StepP { DirP d[2]; int first; };

#define LDA 72                         // padded smem row stride (fp16 elems)
#define T64 (128 * LDA)
#define SMEM_DYN (3 * T64 * 2 + 512)

__global__ __launch_bounds__(256, 2)
void lstm_mma(StepP sp)
{
    extern __shared__ char dyn[];
    float* sBias = (float*)(dyn + 3 * T64 * 2);
    const uint32_t sb = smem_u32(dyn);
    const uint32_t uAh = sb, uAl = sb + T64 * 2, uW = sb + 2 * T64 * 2;
    __half* sAh = (__half*)dyn;
    __half* sAl = sAh + T64;
    __half* sW  = sAl + T64;

    const DirP& P = sp.d[blockIdx.z];
    const int first = sp.first;
    const int tid = threadIdx.x, lane = tid & 31, warp = tid >> 5;
    const int wm = warp >> 2, wn = warp & 3;          // warp grid 2 x 4
    const int b0 = blockIdx.x * 128, n0 = blockIdx.y * 32;

    if (tid < 128) {
        int u = tid >> 2, g = tid & 3;
        int wr = g * 128 + n0 + u;
        sBias[tid] = P.bih[wr] + P.bhh[wr];
    }

    float acc[4][4][4];
#pragma unroll
    for (int i = 0; i < 4; ++i)
#pragma unroll
        for (int j = 0; j < 4; ++j)
#pragma unroll
            for (int k = 0; k < 4; ++k) acc[i][j][k] = 0.f;

    const int nc = first ? P.xchunks : P.nchunks;

    // ldmatrix lane-address components
    const int aRow = (lane & 15), aKo = (lane >> 4) * 8;
    const int bRow = (lane & 7);
    const int bKo  = ((lane >> 3) & 1) * 8;
    const int bNs  = ((lane >> 4) & 1) * 8;

    for (int c = 0; c < nc; ++c) {
        // ---- load 3 tiles global -> smem (16B granules) ----
        {
            const bool isx = (c < P.xchunks);
            const long acol = (long)(isx ? c : (c - P.xchunks)) * 64;
            const long astr = isx ? P.xstride : P.hstride;
            const __half* abh = isx ? P.axh : P.ahh;
            const __half* abl = isx ? P.axl : P.ahl;
#pragma unroll
            for (int it = 0; it < 4; ++it) {
                int idx = tid + it * 256;            // 0..1023
                int row = idx >> 3, gc = idx & 7;
                long go = (long)(b0 + row) * astr + acol + gc * 8;
                uint32_t so = (uint32_t)row * LDA + gc * 8;
                *(uint4*)(sAh + so) = *(const uint4*)(abh + go);
                *(uint4*)(sAl + so) = *(const uint4*)(abl + go);
            }
#pragma unroll
            for (int it = 0; it < 4; ++it) {
                int idx = tid + it * 256;
                int cl = idx >> 3, gc = idx & 7;
                int wr = (cl & 3) * 128 + n0 + (cl >> 2);
                long go = (long)wr * WST + (long)c * 64 + gc * 8;
                uint32_t so = (uint32_t)cl * LDA + gc * 8;
                *(uint4*)(sW + so) = *(const uint4*)(P.w + go);
            }
        }
        __syncthreads();

        // ---- 4 k16 steps; fragments loaded once; 2 combos (Ah*W + Al*W) ----
#pragma unroll
        for (int kk = 0; kk < 4; ++kk) {
            const uint32_t aoff = ((uint32_t)(wm * 64 + aRow) * LDA + kk * 16 + aKo) * 2;
            uint32_t ah[4][4], al[4][4];
#pragma unroll
            for (int mi = 0; mi < 4; ++mi) {
                ldsm_x4(ah[mi][0], ah[mi][1], ah[mi][2], ah[mi][3], uAh + aoff + mi * 16 * LDA * 2);
                ldsm_x4(al[mi][0], al[mi][1], al[mi][2], al[mi][3], uAl + aoff + mi * 16 * LDA * 2);
            }
#pragma unroll
            for (int np = 0; np < 2; ++np) {         // ni pairs {0,1}, {2,3}
                const uint32_t boff = ((uint32_t)(wn * 32 + np * 16 + bNs + bRow) * LDA + kk * 16 + bKo) * 2;
                uint32_t bw[4];
                ldsm_x4(bw[0], bw[1], bw[2], bw[3], uW + boff);
                // pass 1: Ah*W over all 8 acc tiles (long reuse distance)
#pragma unroll
                for (int mi = 0; mi < 4; ++mi) {
                    mma16816(acc[mi][np * 2 + 0], ah[mi], bw + 0);
                    mma16816(acc[mi][np * 2 + 1], ah[mi], bw + 2);
                }
                // pass 2: Al*W
#pragma unroll
                for (int mi = 0; mi < 4; ++mi) {
                    mma16816(acc[mi][np * 2 + 0], al[mi], bw + 0);
                    mma16816(acc[mi][np * 2 + 1], al[mi], bw + 2);
                }
            }
        }
        __syncthreads();
    }

    // ---- epilogue: pair-exchange gates, LSTM pointwise, write h (hi/lo) + c ----
    const bool odd = (lane & 1);
    const int rbase = lane >> 2;
    const int usub = (lane >> 1) & 1;
#pragma unroll
    for (int mi = 0; mi < 4; ++mi) {
#pragma unroll
        for (int ni = 0; ni < 4; ++ni) {
            float c0 = acc[mi][ni][0], c1 = acc[mi][ni][1], c2 = acc[mi][ni][2], c3 = acc[mi][ni][3];
            float s0 = __shfl_xor_sync(0xFFFFFFFFu, c0, 1);
            float s1 = __shfl_xor_sync(0xFFFFFFFFu, c1, 1);
            float s2 = __shfl_xor_sync(0xFFFFFFFFu, c2, 1);
            float s3 = __shfl_xor_sync(0xFFFFFFFFu, c3, 1);
            float vi, vf, vg, vo;
            int r;
            if (!odd) { vi = c0; vf = c1; vg = s0; vo = s1; r = rbase; }
            else      { vi = s2; vf = s3; vg = c2; vo = c3; r = rbase + 8; }
            const int ul = ((wn * 32 + ni * 8) >> 2) + usub;
            const float4 bb = *(const float4*)&sBias[4 * ul];
            vi += bb.x; vf += bb.y; vg += bb.z; vo += bb.w;
            float ig = 1.f / (1.f + __expf(-vi));
            float fg = 1.f / (1.f + __expf(-vf));
            float gg = tanhf(vg);
            float og = 1.f / (1.f + __expf(-vo));
            const long b = b0 + wm * 64 + mi * 16 + r;
            const int gu = n0 + ul;
            float cp = first ? 0.f : P.cbuf[b * HN + gu];
            float cn = fg * cp + ig * gg;
            P.cbuf[b * HN + gu] = cn;
            float h = og * tanhf(cn);
            __half hh = __float2half_rn(h);
            P.oh[b * P.ostride + gu] = hh;
            P.ol[b * P.ostride + gu] = __float2half_rn(h - __half2float(hh));
        }
    }
}

// ------------------------- temporal max-pool -------------------------
__global__ void pool_kernel(const __half* __restrict__ oh,
                            const __half* __restrict__ ol,
                            float* __restrict__ pooled)
{
    long idx = (long)blockIdx.x * blockDim.x + threadIdx.x;
    if (idx >= (long)BSZ * 512) return;
    int b = (int)(idx >> 9);
    int col = (int)(idx & 511);
    int h = col >> 1, p = col & 1;
    long base = ((long)b * TN + p * 5) * 256 + h;
    float m = -1e30f;
#pragma unroll
    for (int s = 0; s < 5; ++s) {
        long i = base + (long)s * 256;
        float v = __half2float(oh[i]) + __half2float(ol[i]);
        m = fmaxf(m, v);
    }
    pooled[idx] = m;
}

// ------------------------- fused FC1(relu)+FC2 -------------------------
__global__ __launch_bounds__(256)
void fc_kernel(const float* __restrict__ pooled,
               const float* __restrict__ w1, const float* __restrict__ b1,
               const float* __restrict__ w2, const float* __restrict__ b2,
               float* __restrict__ outp)
{
    __shared__ float S[64 * 65 + 64 * 64];
    float (*Ws)[65] = (float (*)[65])S;
    float (*Ps)[64] = (float (*)[64])(S + 64 * 65);

    const int tid = threadIdx.x;
    const int b0 = blockIdx.x * 64;
    const int o  = tid & 63;
    const int tg = tid >> 6;

    float acc[16];
#pragma unroll
    for (int r = 0; r < 16; ++r) acc[r] = 0.f;

    for (int kt = 0; kt < 512; kt += 64) {
        for (int e = tid; e < 64 * 64; e += 256) {
            int oo = e >> 6, k = e & 63;
            Ws[k][oo] = w1[(long)oo * 512 + kt + k];
            Ps[oo][k] = pooled[(long)(b0 + oo) * 512 + kt + k];
        }
        __syncthreads();
#pragma unroll 4
        for (int k = 0; k < 64; ++k) {
            float w = Ws[k][o];
#pragma unroll
            for (int r = 0; r < 16; ++r)
                acc[r] = fmaf(Ps[tg * 16 + r][k], w, acc[r]);
        }
        __syncthreads();
    }
    float (*H1)[65] = (float (*)[65])S;
    float bias1 = b1[o];
#pragma unroll
    for (int r = 0; r < 16; ++r)
        H1[tg * 16 + r][o] = fmaxf(acc[r] + bias1, 0.f);
    __syncthreads();
    if (tid < 64) {
        float a2 = b2[0];
#pragma unroll
        for (int oo = 0; oo < 64; ++oo) a2 = fmaf(H1[tid][oo], w2[oo], a2);
        outp[b0 + tid] = a2;
    }
}

// ------------------------- host launcher -------------------------
extern "C" void kernel_launch(void* const* d_in, const int* in_sizes, int n_in,
                              void* d_out, int out_size)
{
    const float* x       = (const float*)d_in[0];
    const float* w_ih1_f = (const float*)d_in[1];
    const float* w_hh1_f = (const float*)d_in[2];
    const float* b_ih1_f = (const float*)d_in[3];
    const float* b_hh1_f = (const float*)d_in[4];
    const float* w_ih1_b = (const float*)d_in[5];
    const float* w_hh1_b = (const float*)d_in[6];
    const float* b_ih1_b = (const float*)d_in[7];
    const float* b_hh1_b = (const float*)d_in[8];
    const float* w_ih2_f = (const float*)d_in[9];
    const float* w_hh2_f = (const float*)d_in[10];
    const float* b_ih2_f = (const float*)d_in[11];
    const float* b_hh2_f = (const float*)d_in[12];
    const float* w_ih2_b = (const float*)d_in[13];
    const float* w_hh2_b = (const float*)d_in[14];
    const float* b_ih2_b = (const float*)d_in[15];
    const float* b_hh2_b = (const float*)d_in[16];
    const float* fc1_w   = (const float*)d_in[17];
    const float* fc1_b   = (const float*)d_in[18];
    const float* fc2_w   = (const float*)d_in[19];
    const float* fc2_b   = (const float*)d_in[20];

    __half *xh, *xl, *o1h, *o1l, *o2h, *o2l, *w;
    float *cf, *cb, *pooled;
    cudaGetSymbolAddress((void**)&xh, g_xh);   cudaGetSymbolAddress((void**)&xl, g_xl);
    cudaGetSymbolAddress((void**)&o1h, g_o1h); cudaGetSymbolAddress((void**)&o1l, g_o1l);
    cudaGetSymbolAddress((void**)&o2h, g_o2h); cudaGetSymbolAddress((void**)&o2l, g_o2l);
    cudaGetSymbolAddress((void**)&w, g_w);
    cudaGetSymbolAddress((void**)&cf, g_cf);   cudaGetSymbolAddress((void**)&cb, g_cb);
    cudaGetSymbolAddress((void**)&pooled, g_pooled);

    cudaFuncSetAttribute(lstm_mma, cudaFuncAttributeMaxDynamicSharedMemorySize, SMEM_DYN);

    {
        long n = (long)BSZ * TN * 192;
        split_x_kernel<<<(unsigned)((n + 255) / 256), 256>>>(x, xh, xl);
        long m = (long)4 * 512 * WST;
        conv_w_kernel<<<(unsigned)((m + 255) / 256), 256>>>(
            w_ih1_f, w_hh1_f, w_ih1_b, w_hh1_b, w_ih2_f, w_hh2_f, w_ih2_b, w_hh2_b, w);
    }

    dim3 grid(BSZ / 128, 4, 2), blk(256);
    const long WCFG = (long)512 * WST;

    // ---- layer 1 ---- (x: 3 chunks of 64, h: 2 chunks)
    for (int t = 0; t < TN; ++t) {
        StepP sp;
        sp.first = (t == 0);
        sp.d[0].axh = xh + (long)t * 192;  sp.d[0].axl = xl + (long)t * 192;
        sp.d[0].ahh = t ? o1h + (long)(t - 1) * 256 : o1h;
        sp.d[0].ahl = t ? o1l + (long)(t - 1) * 256 : o1l;
        sp.d[0].w = w + 0 * WCFG;
        sp.d[0].bih = b_ih1_f; sp.d[0].bhh = b_hh1_f;
        sp.d[0].cbuf = cf;
        sp.d[0].oh = o1h + (long)t * 256; sp.d[0].ol = o1l + (long)t * 256;
        sp.d[0].xstride = (long)TN * 192; sp.d[0].hstride = (long)TN * 256; sp.d[0].ostride = (long)TN * 256;
        sp.d[0].xchunks = 3; sp.d[0].nchunks = 5;
        int tt = TN - 1 - t;
        sp.d[1].axh = xh + (long)tt * 192;  sp.d[1].axl = xl + (long)tt * 192;
        sp.d[1].ahh = t ? o1h + (long)(tt + 1) * 256 + HN : o1h;
        sp.d[1].ahl = t ? o1l + (long)(tt + 1) * 256 + HN : o1l;
        sp.d[1].w = w + 1 * WCFG;
        sp.d[1].bih = b_ih1_b; sp.d[1].bhh = b_hh1_b;
        sp.d[1].cbuf = cb;
        sp.d[1].oh = o1h + (long)tt * 256 + HN; sp.d[1].ol = o1l + (long)tt * 256 + HN;
        sp.d[1].xstride = (long)TN * 192; sp.d[1].hstride = (long)TN * 256; sp.d[1].ostride = (long)TN * 256;
        sp.d[1].xchunks = 3; sp.d[1].nchunks = 5;
        lstm_mma<<<grid, blk, SMEM_DYN>>>(sp);
    }

    // ---- layer 2 ---- (x: 4 chunks, h: 2 chunks)
    for (int t = 0; t < TN; ++t) {
        StepP sp;
        sp.first = (t == 0);
        sp.d[0].axh = o1h + (long)t * 256;  sp.d[0].axl = o1l + (long)t * 256;
        sp.d[0].ahh = t ? o2h + (long)(t - 1) * 256 : o2h;
        sp.d[0].ahl = t ? o2l + (long)(t - 1) * 256 : o2l;
        sp.d[0].w = w + 2 * WCFG;
        sp.d[0].bih = b_ih2_f; sp.d[0].bhh = b_hh2_f;
        sp.d[0].cbuf = cf;
        sp.d[0].oh = o2h + (long)t * 256; sp.d[0].ol = o2l + (long)t * 256;
        sp.d[0].xstride = (long)TN * 256; sp.d[0].hstride = (long)TN * 256; sp.d[0].ostride = (long)TN * 256;
        sp.d[0].xchunks = 4; sp.d[0].nchunks = 6;
        int tt = TN - 1 - t;
        sp.d[1].axh = o1h + (long)tt * 256;  sp.d[1].axl = o1l + (long)tt * 256;
        sp.d[1].ahh = t ? o2h + (long)(tt + 1) * 256 + HN : o2h;
        sp.d[1].ahl = t ? o2l + (long)(tt + 1) * 256 + HN : o2l;
        sp.d[1].w = w + 3 * WCFG;
        sp.d[1].bih = b_ih2_b; sp.d[1].bhh = b_hh2_b;
        sp.d[1].cbuf = cb;
        sp.d[1].oh = o2h + (long)tt * 256 + HN; sp.d[1].ol = o2l + (long)tt * 256 + HN;
        sp.d[1].xstride = (long)TN * 256; sp.d[1].hstride = (long)TN * 256; sp.d[1].ostride = (long)TN * 256;
        sp.d[1].xchunks = 4; sp.d[1].nchunks = 6;
        lstm_mma<<<grid, blk, SMEM_DYN>>>(sp);
    }

    pool_kernel<<<(unsigned)(((long)BSZ * 512 + 255) / 256), 256>>>(o2h, o2l, pooled);
    fc_kernel<<<BSZ / 64, 256>>>(pooled, fc1_w, fc1_b, fc2_w, fc2_b, (float*)d_out);
}

// round 15
// speedup vs baseline: 1.4371x; 1.3813x over previous
#include <cuda_runtime.h>
#include <cuda_fp16.h>
#include <cstdint>
#include <math.h>

#define BSZ 16384
#define TN  10
#define IN_ 184
#define HN  128
#define WST 384          // weight-cat row stride (fp16 elems)

// ------------------------- scratch (__device__ globals) -------------------------
__device__ __half g_x1[(size_t)BSZ * TN * 192];
__device__ __half g_o1[(size_t)BSZ * TN * 256];
__device__ __half g_o2[(size_t)BSZ * TN * 256];
__device__ __half g_w[(size_t)4 * 512 * WST];
__device__ float g_cf[(size_t)BSZ * HN];
__device__ float g_cb[(size_t)BSZ * HN];
__device__ float g_pooled[(size_t)BSZ * 512];

// ------------------------- small helpers -------------------------
__device__ __forceinline__ uint32_t smem_u32(const void* p) {
    uint32_t a;
    asm("{ .reg .u64 t; cvta.to.shared.u64 t, %1; cvt.u32.u64 %0, t; }" : "=r"(a) : "l"(p));
    return a;
}
__device__ __forceinline__ void ldsm_x4(uint32_t& r0, uint32_t& r1, uint32_t& r2, uint32_t& r3, uint32_t addr) {
    asm volatile("ldmatrix.sync.aligned.m8n8.x4.shared.b16 {%0,%1,%2,%3}, [%4];"
                 : "=r"(r0), "=r"(r1), "=r"(r2), "=r"(r3) : "r"(addr));
}
__device__ __forceinline__ void mma16816(float* d, const uint32_t* a, const uint32_t* b) {
    asm volatile("mma.sync.aligned.m16n8k16.row.col.f32.f16.f16.f32 "
                 "{%0,%1,%2,%3}, {%4,%5,%6,%7}, {%8,%9}, {%0,%1,%2,%3};"
                 : "+f"(d[0]), "+f"(d[1]), "+f"(d[2]), "+f"(d[3])
                 : "r"(a[0]), "r"(a[1]), "r"(a[2]), "r"(a[3]), "r"(b[0]), "r"(b[1]));
}

// ------------------------- conversions -------------------------
__global__ void conv_x_kernel(const float* __restrict__ x, __half* __restrict__ xo) {
    long i = (long)blockIdx.x * blockDim.x + threadIdx.x;
    if (i >= (long)BSZ * TN * 192) return;
    int col = (int)(i % 192);
    long bt = i / 192;
    float v = (col < IN_) ? x[bt * IN_ + col] : 0.f;
    xo[i] = __float2half_rn(v);
}

__global__ void conv_w_kernel(const float* __restrict__ a0, const float* __restrict__ h0,
                              const float* __restrict__ a1, const float* __restrict__ h1,
                              const float* __restrict__ a2, const float* __restrict__ h2,
                              const float* __restrict__ a3, const float* __restrict__ h3,
                              __half* __restrict__ w) {
    long i = (long)blockIdx.x * blockDim.x + threadIdx.x;
    if (i >= (long)4 * 512 * WST) return;
    int col = (int)(i % WST);
    int r = (int)((i / WST) % 512);
    int cfg = (int)(i / ((long)512 * WST));
    const float* wih; const float* whh; int kx, hoff;
    switch (cfg) {
        case 0: wih = a0; whh = h0; kx = 184; hoff = 192; break;
        case 1: wih = a1; whh = h1; kx = 184; hoff = 192; break;
        case 2: wih = a2; whh = h2; kx = 256; hoff = 256; break;
        default: wih = a3; whh = h3; kx = 256; hoff = 256; break;
    }
    float v = 0.f;
    if (col < kx)                             v = wih[(long)r * kx + col];
    else if (col >= hoff && col < hoff + 128) v = whh[(long)r * 128 + (col - hoff)];
    w[i] = __float2half_rn(v);
}

// ------------------------- fused HMMA LSTM step -------------------------
// Block tile: 128 batch rows x 64 cols (16 units x 4 gates, col = 4*unit + gate).
// 256 threads = 8 warps in 2(m) x 4(n); warp tile 64 x 16. Pure fp16, 1 combo.
struct DirP {
    const __half *ax;                 // x-part base (offset to this step's t)
    const __half *ah;                 // h-part base; unused if first
    const __half *w;                  // weight-cat [512][WST]
    const float *bih, *bhh;
    float* cbuf;
    __half *o;                        // out base (offset to t + dir col)
    long xstride, hstride, ostride;
    int xchunks, nchunks;             // in 64-col chunks
};
struct StepP { DirP d[2]; int first; };

#define LDA 72                         // padded smem row stride (fp16 elems)
#define T_A (128 * LDA)
#define T_W (64 * LDA)
#define SMEM_DYN ((T_A + T_W) * 2 + 512)

__global__ __launch_bounds__(256, 4)
void lstm_mma(StepP sp)
{
    extern __shared__ char dyn[];
    float* sBias = (float*)(dyn + (T_A + T_W) * 2);
    const uint32_t sb = smem_u32(dyn);
    const uint32_t uA = sb, uW = sb + T_A * 2;
    __half* sA = (__half*)dyn;
    __half* sW = sA + T_A;

    const DirP& P = sp.d[blockIdx.z];
    const int first = sp.first;
    const int tid = threadIdx.x, lane = tid & 31, warp = tid >> 5;
    const int wm = warp >> 2, wn = warp & 3;          // warp grid 2(m) x 4(n)
    const int b0 = blockIdx.x * 128;
    const int n0u = blockIdx.y * 16;                  // first unit of this block

    if (tid < 64) {
        int u = tid >> 2, g = tid & 3;
        int wr = g * 128 + n0u + u;
        sBias[tid] = P.bih[wr] + P.bhh[wr];
    }

    float acc[4][2][4];
#pragma unroll
    for (int i = 0; i < 4; ++i)
#pragma unroll
        for (int j = 0; j < 2; ++j)
#pragma unroll
            for (int k = 0; k < 4; ++k) acc[i][j][k] = 0.f;

    const int nc = first ? P.xchunks : P.nchunks;

    // ldmatrix lane-address components
    const int aRow = (lane & 15), aKo = (lane >> 4) * 8;
    const int bRow = (lane & 7);
    const int bKo  = ((lane >> 3) & 1) * 8;
    const int bNs  = ((lane >> 4) & 1) * 8;

    for (int c = 0; c < nc; ++c) {
        // ---- load A (128x64) + W (64x64) tiles global -> smem ----
        {
            const bool isx = (c < P.xchunks);
            const long acol = (long)(isx ? c : (c - P.xchunks)) * 64;
            const long astr = isx ? P.xstride : P.hstride;
            const __half* ab = isx ? P.ax : P.ah;
#pragma unroll
            for (int it = 0; it < 4; ++it) {
                int idx = tid + it * 256;            // 0..1023 granules
                int row = idx >> 3, gc = idx & 7;
                long go = (long)(b0 + row) * astr + acol + gc * 8;
                *(uint4*)(sA + (uint32_t)row * LDA + gc * 8) = *(const uint4*)(ab + go);
            }
#pragma unroll
            for (int it = 0; it < 2; ++it) {
                int idx = tid + it * 256;            // 0..511 granules
                int cl = idx >> 3, gc = idx & 7;
                int wr = (cl & 3) * 128 + n0u + (cl >> 2);
                long go = (long)wr * WST + (long)c * 64 + gc * 8;
                *(uint4*)(sW + (uint32_t)cl * LDA + gc * 8) = *(const uint4*)(P.w + go);
            }
        }
        __syncthreads();

        // ---- 4 k16 steps ----
#pragma unroll
        for (int kk = 0; kk < 4; ++kk) {
            uint32_t bw[4];
            const uint32_t boff = ((uint32_t)(wn * 16 + bNs + bRow) * LDA + kk * 16 + bKo) * 2;
            ldsm_x4(bw[0], bw[1], bw[2], bw[3], uW + boff);
            const uint32_t aoff = ((uint32_t)(wm * 64 + aRow) * LDA + kk * 16 + aKo) * 2;
#pragma unroll
            for (int mi = 0; mi < 4; ++mi) {
                uint32_t a[4];
                ldsm_x4(a[0], a[1], a[2], a[3], uA + aoff + mi * 16 * LDA * 2);
                mma16816(acc[mi][0], a, bw + 0);
                mma16816(acc[mi][1], a, bw + 2);
            }
        }
        __syncthreads();
    }

    // ---- epilogue: pair-exchange gates, LSTM pointwise, write h + c ----
    const bool odd = (lane & 1);
    const int rbase = lane >> 2;
    const int usub = (lane >> 1) & 1;
#pragma unroll
    for (int mi = 0; mi < 4; ++mi) {
#pragma unroll
        for (int ni = 0; ni < 2; ++ni) {
            float c0 = acc[mi][ni][0], c1 = acc[mi][ni][1], c2 = acc[mi][ni][2], c3 = acc[mi][ni][3];
            float s0 = __shfl_xor_sync(0xFFFFFFFFu, c0, 1);
            float s1 = __shfl_xor_sync(0xFFFFFFFFu, c1, 1);
            float s2 = __shfl_xor_sync(0xFFFFFFFFu, c2, 1);
            float s3 = __shfl_xor_sync(0xFFFFFFFFu, c3, 1);
            float vi, vf, vg, vo;
            int r;
            if (!odd) { vi = c0; vf = c1; vg = s0; vo = s1; r = rbase; }
            else      { vi = s2; vf = s3; vg = c2; vo = c3; r = rbase + 8; }
            const int ul = wn * 4 + ni * 2 + usub;           // unit local 0..15
            const float4 bb = *(const float4*)&sBias[4 * ul];
            vi += bb.x; vf += bb.y; vg += bb.z; vo += bb.w;
            float ig = 1.f / (1.f + __expf(-vi));
            float fg = 1.f / (1.f + __expf(-vf));
            float gg = tanhf(vg);
            float og = 1.f / (1.f + __expf(-vo));
            const long b = b0 + wm * 64 + mi * 16 + r;
            const int gu = n0u + ul;
            float cp = first ? 0.f : P.cbuf[b * HN + gu];
            float cn = fg * cp + ig * gg;
            P.cbuf[b * HN + gu] = cn;
            float h = og * tanhf(cn);
            P.o[b * P.ostride + gu] = __float2half_rn(h);
        }
    }
}

// ------------------------- temporal max-pool -------------------------
__global__ void pool_kernel(const __half* __restrict__ o2, float* __restrict__ pooled)
{
    long idx = (long)blockIdx.x * blockDim.x + threadIdx.x;
    if (idx >= (long)BSZ * 512) return;
    int b = (int)(idx >> 9);
    int col = (int)(idx & 511);
    int h = col >> 1, p = col & 1;
    long base = ((long)b * TN + p * 5) * 256 + h;
    float m = -1e30f;
#pragma unroll
    for (int s = 0; s < 5; ++s)
        m = fmaxf(m, __half2float(o2[base + (long)s * 256]));
    pooled[idx] = m;
}

// ------------------------- fused FC1(relu)+FC2 -------------------------
__global__ __launch_bounds__(256)
void fc_kernel(const float* __restrict__ pooled,
               const float* __restrict__ w1, const float* __restrict__ b1,
               const float* __restrict__ w2, const float* __restrict__ b2,
               float* __restrict__ outp)
{
    __shared__ float S[64 * 65 + 64 * 64];
    float (*Ws)[65] = (float (*)[65])S;
    float (*Ps)[64] = (float (*)[64])(S + 64 * 65);

    const int tid = threadIdx.x;
    const int b0 = blockIdx.x * 64;
    const int o  = tid & 63;
    const int tg = tid >> 6;

    float acc[16];
#pragma unroll
    for (int r = 0; r < 16; ++r) acc[r] = 0.f;

    for (int kt = 0; kt < 512; kt += 64) {
        for (int e = tid; e < 64 * 64; e += 256) {
            int oo = e >> 6, k = e & 63;
            Ws[k][oo] = w1[(long)oo * 512 + kt + k];
            Ps[oo][k] = pooled[(long)(b0 + oo) * 512 + kt + k];
        }
        __syncthreads();
#pragma unroll 4
        for (int k = 0; k < 64; ++k) {
            float w = Ws[k][o];
#pragma unroll
            for (int r = 0; r < 16; ++r)
                acc[r] = fmaf(Ps[tg * 16 + r][k], w, acc[r]);
        }
        __syncthreads();
    }
    float (*H1)[65] = (float (*)[65])S;
    float bias1 = b1[o];
#pragma unroll
    for (int r = 0; r < 16; ++r)
        H1[tg * 16 + r][o] = fmaxf(acc[r] + bias1, 0.f);
    __syncthreads();
    if (tid < 64) {
        float a2 = b2[0];
#pragma unroll
        for (int oo = 0; oo < 64; ++oo) a2 = fmaf(H1[tid][oo], w2[oo], a2);
        outp[b0 + tid] = a2;
    }
}

// ------------------------- host launcher -------------------------
extern "C" void kernel_launch(void* const* d_in, const int* in_sizes, int n_in,
                              void* d_out, int out_size)
{
    const float* x       = (const float*)d_in[0];
    const float* w_ih1_f = (const float*)d_in[1];
    const float* w_hh1_f = (const float*)d_in[2];
    const float* b_ih1_f = (const float*)d_in[3];
    const float* b_hh1_f = (const float*)d_in[4];
    const float* w_ih1_b = (const float*)d_in[5];
    const float* w_hh1_b = (const float*)d_in[6];
    const float* b_ih1_b = (const float*)d_in[7];
    const float* b_hh1_b = (const float*)d_in[8];
    const float* w_ih2_f = (const float*)d_in[9];
    const float* w_hh2_f = (const float*)d_in[10];
    const float* b_ih2_f = (const float*)d_in[11];
    const float* b_hh2_f = (const float*)d_in[12];
    const float* w_ih2_b = (const float*)d_in[13];
    const float* w_hh2_b = (const float*)d_in[14];
    const float* b_ih2_b = (const float*)d_in[15];
    const float* b_hh2_b = (const float*)d_in[16];
    const float* fc1_w   = (const float*)d_in[17];
    const float* fc1_b   = (const float*)d_in[18];
    const float* fc2_w   = (const float*)d_in[19];
    const float* fc2_b   = (const float*)d_in[20];

    __half *x1, *o1, *o2, *w;
    float *cf, *cb, *pooled;
    cudaGetSymbolAddress((void**)&x1, g_x1);
    cudaGetSymbolAddress((void**)&o1, g_o1);
    cudaGetSymbolAddress((void**)&o2, g_o2);
    cudaGetSymbolAddress((void**)&w, g_w);
    cudaGetSymbolAddress((void**)&cf, g_cf);   cudaGetSymbolAddress((void**)&cb, g_cb);
    cudaGetSymbolAddress((void**)&pooled, g_pooled);

    cudaFuncSetAttribute(lstm_mma, cudaFuncAttributeMaxDynamicSharedMemorySize, SMEM_DYN);

    {
        long n = (long)BSZ * TN * 192;
        conv_x_kernel<<<(unsigned)((n + 255) / 256), 256>>>(x, x1);
        long m = (long)4 * 512 * WST;
        conv_w_kernel<<<(unsigned)((m + 255) / 256), 256>>>(
            w_ih1_f, w_hh1_f, w_ih1_b, w_hh1_b, w_ih2_f, w_hh2_f, w_ih2_b, w_hh2_b, w);
    }

    dim3 grid(BSZ / 128, 8, 2), blk(256);
    const long WCFG = (long)512 * WST;

    // ---- layer 1 ---- (x: 3 chunks of 64, h: 2 chunks)
    for (int t = 0; t < TN; ++t) {
        StepP sp;
        sp.first = (t == 0);
        sp.d[0].ax = x1 + (long)t * 192;
        sp.d[0].ah = t ? o1 + (long)(t - 1) * 256 : o1;
        sp.d[0].w = w + 0 * WCFG;
        sp.d[0].bih = b_ih1_f; sp.d[0].bhh = b_hh1_f;
        sp.d[0].cbuf = cf;
        sp.d[0].o = o1 + (long)t * 256;
        sp.d[0].xstride = (long)TN * 192; sp.d[0].hstride = (long)TN * 256; sp.d[0].ostride = (long)TN * 256;
        sp.d[0].xchunks = 3; sp.d[0].nchunks = 5;
        int tt = TN - 1 - t;
        sp.d[1].ax = x1 + (long)tt * 192;
        sp.d[1].ah = t ? o1 + (long)(tt + 1) * 256 + HN : o1;
        sp.d[1].w = w + 1 * WCFG;
        sp.d[1].bih = b_ih1_b; sp.d[1].bhh = b_hh1_b;
        sp.d[1].cbuf = cb;
        sp.d[1].o = o1 + (long)tt * 256 + HN;
        sp.d[1].xstride = (long)TN * 192; sp.d[1].hstride = (long)TN * 256; sp.d[1].ostride = (long)TN * 256;
        sp.d[1].xchunks = 3; sp.d[1].nchunks = 5;
        lstm_mma<<<grid, blk, SMEM_DYN>>>(sp);
    }

    // ---- layer 2 ---- (x: 4 chunks, h: 2 chunks)
    for (int t = 0; t < TN; ++t) {
        StepP sp;
        sp.first = (t == 0);
        sp.d[0].ax = o1 + (long)t * 256;
        sp.d[0].ah = t ? o2 + (long)(t - 1) * 256 : o2;
        sp.d[0].w = w + 2 * WCFG;
        sp.d[0].bih = b_ih2_f; sp.d[0].bhh = b_hh2_f;
        sp.d[0].cbuf = cf;
        sp.d[0].o = o2 + (long)t * 256;
        sp.d[0].xstride = (long)TN * 256; sp.d[0].hstride = (long)TN * 256; sp.d[0].ostride = (long)TN * 256;
        sp.d[0].xchunks = 4; sp.d[0].nchunks = 6;
        int tt = TN - 1 - t;
        sp.d[1].ax = o1 + (long)tt * 256;
        sp.d[1].ah = t ? o2 + (long)(tt + 1) * 256 + HN : o2;
        sp.d[1].w = w + 3 * WCFG;
        sp.d[1].bih = b_ih2_b; sp.d[1].bhh = b_hh2_b;
        sp.d[1].cbuf = cb;
        sp.d[1].o = o2 + (long)tt * 256 + HN;
        sp.d[1].xstride = (long)TN * 256; sp.d[1].hstride = (long)TN * 256; sp.d[1].ostride = (long)TN * 256;
        sp.d[1].xchunks = 4; sp.d[1].nchunks = 6;
        lstm_mma<<<grid, blk, SMEM_DYN>>>(sp);
    }

    pool_kernel<<<(unsigned)(((long)BSZ * 512 + 255) / 256), 256>>>(o2, pooled);
    fc_kernel<<<BSZ / 64, 256>>>(pooled, fc1_w, fc1_b, fc2_w, fc2_b, (float*)d_out);
}